// round 1
// baseline (speedup 1.0000x reference)
#include <cuda_runtime.h>
#include <math.h>

#define T_LEN 8192
#define E_DIM 1024
#define D_DIM 1028
#define NTAG  50

// Scratch (static __device__ globals: allocation-free per harness rules)
__device__ float g_A[T_LEN * 16];   // per-step gate angles (bias + theta folded in)
__device__ float g_H[T_LEN * 4];    // per-step hidden state

__device__ __forceinline__ float tanh_ap(float x) {
    float y;
    asm("tanh.approx.f32 %0, %1;" : "=f"(y) : "f"(x));
    return y;
}

// ---------------------------------------------------------------------------
// Kernel 1: A[t, g*4+w] = b_g[w] + th_g[w] + sum_e emb[sent[t],e] * W_g[w,e]
// Block: 512 threads = 16 warps = 16 outputs; 8 tokens per block (register tile).
// ---------------------------------------------------------------------------
__global__ __launch_bounds__(512) void k_pre(
    const int*   __restrict__ sent, const float* __restrict__ emb,
    const float* __restrict__ Wf,  const float* __restrict__ bf,
    const float* __restrict__ Wi,  const float* __restrict__ bi,
    const float* __restrict__ Wu,  const float* __restrict__ bu,
    const float* __restrict__ Wo,  const float* __restrict__ bo,
    const float* __restrict__ thf, const float* __restrict__ thi,
    const float* __restrict__ thu, const float* __restrict__ tho)
{
    const int warp = threadIdx.x >> 5;          // 0..15  -> output index
    const int lane = threadIdx.x & 31;
    const int tokg = blockIdx.x;                // token group (8 tokens)
    const int out  = warp;
    const int g    = out >> 2, w = out & 3;

    const float* Wg = (g == 0) ? Wf : (g == 1) ? Wi : (g == 2) ? Wu : Wo;
    const float* bg = (g == 0) ? bf : (g == 1) ? bi : (g == 2) ? bu : bo;
    const float* tg = (g == 0) ? thf : (g == 1) ? thi : (g == 2) ? thu : tho;

    const float4* wrow = (const float4*)(Wg + w * D_DIM);

    const float4* xrow[8];
    #pragma unroll
    for (int tk = 0; tk < 8; tk++) {
        int tok = tokg * 8 + tk;
        xrow[tk] = (const float4*)(emb + (size_t)__ldg(sent + tok) * E_DIM);
    }

    float acc[8];
    #pragma unroll
    for (int tk = 0; tk < 8; tk++) acc[tk] = 0.f;

    // 256 float4 per row; 32 lanes -> 8 j-iterations, fully coalesced
    #pragma unroll
    for (int j = 0; j < 8; j++) {
        int e4 = j * 32 + lane;
        float4 wv = __ldg(wrow + e4);
        #pragma unroll
        for (int tk = 0; tk < 8; tk++) {
            float4 xv = __ldg(xrow[tk] + e4);
            acc[tk] = fmaf(xv.x, wv.x, acc[tk]);
            acc[tk] = fmaf(xv.y, wv.y, acc[tk]);
            acc[tk] = fmaf(xv.z, wv.z, acc[tk]);
            acc[tk] = fmaf(xv.w, wv.w, acc[tk]);
        }
    }

    // warp reduction per token accumulator
    #pragma unroll
    for (int tk = 0; tk < 8; tk++) {
        float v = acc[tk];
        #pragma unroll
        for (int off = 16; off; off >>= 1)
            v += __shfl_xor_sync(0xffffffffu, v, off);
        acc[tk] = v;
    }

    if (lane == 0) {
        float add = __ldg(bg + w) + __ldg(tg + w);
        #pragma unroll
        for (int tk = 0; tk < 8; tk++) {
            int tok = tokg * 8 + tk;
            g_A[tok * 16 + out] = acc[tk] + add;
        }
    }
}

// ---------------------------------------------------------------------------
// Kernel 2: the serial LSTM scan. 1 block, 16 active lanes: lane = g*4 + w.
// qlayer closed form: y = product of cos(angle) over wire subsets.
// ---------------------------------------------------------------------------
__global__ __launch_bounds__(32) void k_scan(
    const float* __restrict__ Wf, const float* __restrict__ Wi,
    const float* __restrict__ Wu, const float* __restrict__ Wo)
{
    const int lane = threadIdx.x;
    if (lane >= 16) return;
    const unsigned M = 0xFFFFu;

    const int w  = lane & 3;
    const int g  = lane >> 2;
    const int gb = lane & ~3;

    const float* Wg = (g == 0) ? Wf : (g == 1) ? Wi : (g == 2) ? Wu : Wo;
    // recurrent 4-weights for this (gate, wire): columns 1024..1027 of row w
    const float4 wh = *(const float4*)(Wg + w * D_DIM + E_DIM);

    // activation: sigmoid = 0.5 + 0.5*tanh(0.5*y); tanh gate (g==2) direct
    const float A1 = (g == 2) ? 1.0f : 0.5f;
    const float A0 = (g == 2) ? 0.0f : 0.5f;
    const float K  = (g == 2) ? 1.0f : 0.5f;

    float h = 0.f, c = 0.f;
    const float* Ap = g_A + lane;

    // prefetch pipeline (depth 4); A sits in L2 (512 KB)
    float b0 = __ldg(Ap + 0 * 16);
    float b1 = __ldg(Ap + 1 * 16);
    float b2 = __ldg(Ap + 2 * 16);
    float b3 = __ldg(Ap + 3 * 16);

#define SCAN_STEP(TT, ABUF)                                                    \
    do {                                                                       \
        float h0 = __shfl_sync(M, h, gb + 0);                                  \
        float h1 = __shfl_sync(M, h, gb + 1);                                  \
        float h2 = __shfl_sync(M, h, gb + 2);                                  \
        float h3 = __shfl_sync(M, h, gb + 3);                                  \
        float pre = ABUF;                                                      \
        pre = fmaf(wh.x, h0, pre);                                             \
        pre = fmaf(wh.y, h1, pre);                                             \
        pre = fmaf(wh.z, h2, pre);                                             \
        pre = fmaf(wh.w, h3, pre);                                             \
        float C  = __cosf(pre);                                                \
        float C0 = __shfl_sync(M, C, gb + 0);                                  \
        float C1 = __shfl_sync(M, C, gb + 1);                                  \
        float C2 = __shfl_sync(M, C, gb + 2);                                  \
        float C3 = __shfl_sync(M, C, gb + 3);                                  \
        float u23 = C2 * C3;                                                   \
        float p01 = C0 * C1;                                                   \
        float y = (w == 0) ? C1 * u23 : (w == 1) ? p01                         \
                : (w == 2) ? p01 * C2 : p01 * u23;                             \
        float act = fmaf(A1, tanh_ap(K * y), A0);                              \
        float fv = __shfl_sync(M, act, w + 0);                                 \
        float iv = __shfl_sync(M, act, w + 4);                                 \
        float gv = __shfl_sync(M, act, w + 8);                                 \
        float ov = __shfl_sync(M, act, w + 12);                                \
        c = fmaf(fv, c, iv * gv);                                              \
        h = ov * tanh_ap(c);                                                   \
        if (g == 0) g_H[(TT) * 4 + w] = h;                                     \
        ABUF = __ldg(Ap + (size_t)(((TT) + 4) & (T_LEN - 1)) * 16);            \
    } while (0)

    for (int tb = 0; tb < T_LEN; tb += 4) {
        SCAN_STEP(tb + 0, b0);
        SCAN_STEP(tb + 1, b1);
        SCAN_STEP(tb + 2, b2);
        SCAN_STEP(tb + 3, b3);
    }
#undef SCAN_STEP
}

// ---------------------------------------------------------------------------
// Kernel 3: tag logits + log_softmax. One warp per token.
// Lane j handles tags j and j+32 (valid when < 50).
// ---------------------------------------------------------------------------
__global__ __launch_bounds__(256) void k_out(
    const float* __restrict__ Wt, const float* __restrict__ bt,
    float* __restrict__ outp)
{
    const int gwarp = (blockIdx.x * blockDim.x + threadIdx.x) >> 5;
    const int lane  = threadIdx.x & 31;
    if (gwarp >= T_LEN) return;

    const float4 h = *(const float4*)(g_H + gwarp * 4);

    float l0;
    {
        const float4 wr = *(const float4*)(Wt + lane * 4);
        l0 = __ldg(bt + lane);
        l0 = fmaf(h.x, wr.x, l0);
        l0 = fmaf(h.y, wr.y, l0);
        l0 = fmaf(h.z, wr.z, l0);
        l0 = fmaf(h.w, wr.w, l0);
    }
    const bool v1 = (lane + 32) < NTAG;
    float l1 = __int_as_float(0xff800000);  // -inf
    if (v1) {
        const float4 wr = *(const float4*)(Wt + (lane + 32) * 4);
        l1 = __ldg(bt + lane + 32);
        l1 = fmaf(h.x, wr.x, l1);
        l1 = fmaf(h.y, wr.y, l1);
        l1 = fmaf(h.z, wr.z, l1);
        l1 = fmaf(h.w, wr.w, l1);
    }

    float m = fmaxf(l0, l1);
    #pragma unroll
    for (int off = 16; off; off >>= 1)
        m = fmaxf(m, __shfl_xor_sync(0xffffffffu, m, off));

    float s = expf(l0 - m) + (v1 ? expf(l1 - m) : 0.f);
    #pragma unroll
    for (int off = 16; off; off >>= 1)
        s += __shfl_xor_sync(0xffffffffu, s, off);

    const float lse = m + logf(s);

    outp[gwarp * NTAG + lane] = l0 - lse;
    if (v1) outp[gwarp * NTAG + lane + 32] = l1 - lse;
}

// ---------------------------------------------------------------------------
extern "C" void kernel_launch(void* const* d_in, const int* in_sizes, int n_in,
                              void* d_out, int out_size)
{
    const int*   sent = (const int*)  d_in[0];
    const float* emb  = (const float*)d_in[1];
    const float* Wf   = (const float*)d_in[2];
    const float* bf   = (const float*)d_in[3];
    const float* Wi   = (const float*)d_in[4];
    const float* bi   = (const float*)d_in[5];
    const float* Wu   = (const float*)d_in[6];
    const float* bu   = (const float*)d_in[7];
    const float* Wo   = (const float*)d_in[8];
    const float* bo   = (const float*)d_in[9];
    const float* thf  = (const float*)d_in[10];
    const float* thi  = (const float*)d_in[11];
    const float* thu  = (const float*)d_in[12];
    const float* tho  = (const float*)d_in[13];
    const float* Wt   = (const float*)d_in[14];
    const float* bt   = (const float*)d_in[15];
    float* outp = (float*)d_out;

    k_pre<<<T_LEN / 8, 512>>>(sent, emb, Wf, bf, Wi, bi, Wu, bu, Wo, bo,
                              thf, thi, thu, tho);
    k_scan<<<1, 32>>>(Wf, Wi, Wu, Wo);
    k_out<<<T_LEN / 8, 256>>>(Wt, bt, outp);
}